// round 8
// baseline (speedup 1.0000x reference)
#include <cuda_runtime.h>
#include <math.h>

#define SETS 32   // B*M
#define NI   128  // N
#define DD   32   // D
#define KK   64   // 2D
#define HH   64   // H
#define JT   8    // j-tile in k2a

#define WTP  36   // padded stride for transposed [k][32] weight tiles (float4-aligned)
#define XNP  36   // padded stride for 32-float row tiles
#define HP   72   // padded stride for 64-float h rows

// Scratch (allocation-free rule: __device__ globals)
__device__ __align__(16) float g_x1  [SETS * NI * DD];
__device__ __align__(16) float g_A   [SETS * NI * KK];
__device__ __align__(16) float g_Bneg[SETS * NI * KK];
__device__ __align__(16) float g_Sp  [2 * SETS * NI * NI];   // k-split partial S
__device__ float g_mask[SETS * NI];
__device__ float g_mean[SETS];
__device__ float g_rstd[SETS];
__device__ float g_v2[KK];
__device__ float g_c2;

__device__ __forceinline__ float gelu_t(float x) {
    float u = x * fmaf(0.044715f * 0.7978845608028654f, x * x, 0.7978845608028654f);
    float th;
    asm("tanh.approx.f32 %0, %1;" : "=f"(th) : "f"(u));
    float hx = 0.5f * x;
    return fmaf(hx, th, hx);
}

// ---- packed f32x2 helpers ----
__device__ __forceinline__ unsigned long long pk2(float lo, float hi) {
    unsigned long long r;
    asm("mov.b64 %0, {%1,%2};" : "=l"(r) : "f"(lo), "f"(hi));
    return r;
}
#define ADD2(o,a,b)   asm("add.rn.f32x2 %0, %1, %2;"     : "=l"(o) : "l"(a), "l"(b))
#define MUL2(o,a,b)   asm("mul.rn.f32x2 %0, %1, %2;"     : "=l"(o) : "l"(a), "l"(b))
#define FMA2(o,a,b,c) asm("fma.rn.f32x2 %0, %1, %2, %3;" : "=l"(o) : "l"(a), "l"(b), "l"(c))

__device__ __forceinline__ unsigned long long gelu2_dot(
    unsigned long long a2, unsigned long long bneg2, unsigned long long v2,
    unsigned long long acc2, unsigned long long C0_2, unsigned long long C1_2,
    unsigned long long H_2)
{
    unsigned long long t2, xx2, w2, u2, th2, hx2, g2;
    ADD2(t2, a2, bneg2);
    MUL2(xx2, t2, t2);
    FMA2(w2, xx2, C1_2, C0_2);
    MUL2(u2, t2, w2);
    float u0, u1, t0, t1;
    asm("mov.b64 {%0,%1}, %2;" : "=f"(u0), "=f"(u1) : "l"(u2));
    asm("tanh.approx.f32 %0, %1;" : "=f"(t0) : "f"(u0));
    asm("tanh.approx.f32 %0, %1;" : "=f"(t1) : "f"(u1));
    asm("mov.b64 %0, {%1,%2};" : "=l"(th2) : "f"(t0), "f"(t1));
    MUL2(hx2, t2, H_2);
    FMA2(g2, hx2, th2, hx2);
    FMA2(acc2, g2, v2, acc2);
    return acc2;
}

// Kernel 0: per-set stats (mean, rstd), mask; fold w3 through W2b/b2b.
// Grid = SETS x 128 threads; thread = row.
__global__ __launch_bounds__(128) void k0_stats(
    const float* __restrict__ x, const float* __restrict__ xsz,
    const float* __restrict__ W2b, const float* __restrict__ b2b,
    const float* __restrict__ w3)
{
    const int s = blockIdx.x;
    const int tid = threadIdx.x;
    __shared__ float red[4];

    float lsum = 0.f; int anynz = 0;
    const float4* xp = (const float4*)(x + ((size_t)s * NI + tid) * DD);
    float4 xv[8];
    #pragma unroll
    for (int q = 0; q < 8; q++) {
        xv[q] = xp[q];
        lsum += xv[q].x + xv[q].y + xv[q].z + xv[q].w;
        anynz |= (xv[q].x != 0.f) | (xv[q].y != 0.f) | (xv[q].z != 0.f) | (xv[q].w != 0.f);
    }
    const float mk = anynz ? 1.f : 0.f;
    g_mask[s * NI + tid] = mk;

    // block sum
    float v = lsum;
    #pragma unroll
    for (int o = 16; o > 0; o >>= 1) v += __shfl_down_sync(0xffffffffu, v, o);
    if ((tid & 31) == 0) red[tid >> 5] = v;
    __syncthreads();
    const float denom = xsz[s >> 3] * (float)DD;
    const float mean = (red[0] + red[1] + red[2] + red[3]) / denom;
    __syncthreads();

    float lv = 0.f;
    #pragma unroll
    for (int q = 0; q < 8; q++) {
        float a = xv[q].x - mean, b = xv[q].y - mean, c = xv[q].z - mean, e = xv[q].w - mean;
        lv += a * a + b * b + c * c + e * e;
    }
    lv *= mk;
    v = lv;
    #pragma unroll
    for (int o = 16; o > 0; o >>= 1) v += __shfl_down_sync(0xffffffffu, v, o);
    if ((tid & 31) == 0) red[tid >> 5] = v;
    __syncthreads();
    if (tid == 0) {
        const float var = red[0] + red[1] + red[2] + red[3];
        g_mean[s] = mean;
        g_rstd[s] = 1.f / (sqrtf(var / denom) + 1e-8f);
    }

    if (s == 0) {
        if (tid < KK) {
            float a = 0.f;
            for (int h = 0; h < HH; h++) a = fmaf(W2b[tid * HH + h], w3[h], a);
            g_v2[tid] = a;
        }
        if (tid == KK) {
            float a = 0.f;
            for (int h = 0; h < HH; h++) a = fmaf(b2b[h], w3[h], a);
            g_c2 = a;
        }
    }
}

// Kernel 1: set_norm + MLP1 + A/Bneg, phase-based, zero shuffles.
// Grid = SETS*8 blocks x 128 threads; block = 16 rows; thread (rl = tid>>3, p = tid&7).
__global__ __launch_bounds__(128) void k1_prep(
    const float* __restrict__ x,
    const float* __restrict__ W1a, const float* __restrict__ b1a,
    const float* __restrict__ W1b, const float* __restrict__ b1b,
    const float* __restrict__ W2a, const float* __restrict__ b2a)
{
    const int s    = blockIdx.x >> 3;
    const int tile = blockIdx.x & 7;
    const int tid  = threadIdx.x;
    const int rl   = tid >> 3;
    const int p    = tid & 7;
    const int row  = tile * 16 + rl;
    const size_t grow = (size_t)s * NI + row;

    __shared__ __align__(16) float sW1aT[KK * WTP];  // [k][d]
    __shared__ __align__(16) float sW2aT[KK * WTP];  // [k][d]
    __shared__ __align__(16) float sW1b [KK * WTP];  // [k][d] natural
    __shared__ __align__(16) float sXn[16 * XNP];
    __shared__ __align__(16) float sX1[16 * XNP];
    __shared__ __align__(16) float sH [16 * HP];
    __shared__ float sb1a[KK], sb2a[KK], sb1b[DD];

    // stage weights (coalesced LDG; transposed STS)
    for (int i = tid; i < KK * DD; i += 128) {
        const int d = i >> 6, k = i & 63;         // W1a/W2a linear = d*64 + k
        sW1aT[k * WTP + d] = W1a[i];
        sW2aT[k * WTP + d] = W2a[i];
        const int kb = i >> 5, db = i & 31;       // W1b linear = k*32 + d
        sW1b[kb * WTP + db] = W1b[i];
    }
    if (tid < KK) { sb1a[tid] = b1a[tid]; sb2a[tid] = b2a[tid]; }
    if (tid < DD) sb1b[tid] = b1b[tid];

    const float mean = g_mean[s];
    const float mk   = g_mask[grow];
    const float inv  = mk * g_rstd[s];

    // Phase A: xn -> smem (thread: 4 d's)
    {
        const float4 xv = *(const float4*)(x + grow * DD + p * 4);
        float4 o;
        o.x = (xv.x - mean) * inv; o.y = (xv.y - mean) * inv;
        o.z = (xv.z - mean) * inv; o.w = (xv.w - mean) * inv;
        *(float4*)&sXn[rl * XNP + p * 4] = o;
    }
    __syncthreads();

    // Phase B: h[rl][k] = gelu(b1a[k] + xn_row . W1aT[k])   (thread: 8 k's)
    {
        float xnr[DD];
        const float4* xr4 = (const float4*)&sXn[rl * XNP];
        #pragma unroll
        for (int q = 0; q < 8; q++) {
            float4 v = xr4[q];
            xnr[4*q+0] = v.x; xnr[4*q+1] = v.y; xnr[4*q+2] = v.z; xnr[4*q+3] = v.w;
        }
        #pragma unroll
        for (int kk = 0; kk < 8; kk++) {
            const int k = p + 8 * kk;
            const float4* w4 = (const float4*)&sW1aT[k * WTP];
            float aa = sb1a[k];
            #pragma unroll
            for (int q = 0; q < 8; q++) {
                float4 v = w4[q];
                aa = fmaf(xnr[4*q+0], v.x, aa);
                aa = fmaf(xnr[4*q+1], v.y, aa);
                aa = fmaf(xnr[4*q+2], v.z, aa);
                aa = fmaf(xnr[4*q+3], v.w, aa);
            }
            sH[rl * HP + k] = gelu_t(aa);
        }
    }
    __syncthreads();

    // Phase C: x1[rl][d] = mk*(b1b[d] + sum_k h[rl][k]*W1b[k][d])  (thread: 4 d's)
    {
        const int d0 = p * 4;
        float a0 = sb1b[d0], a1 = sb1b[d0+1], a2_ = sb1b[d0+2], a3 = sb1b[d0+3];
        const float* hrow = &sH[rl * HP];
        #pragma unroll 8
        for (int k = 0; k < KK; k++) {
            const float hv = hrow[k];
            const float4 w = *(const float4*)&sW1b[k * WTP + d0];
            a0 = fmaf(hv, w.x, a0);
            a1 = fmaf(hv, w.y, a1);
            a2_ = fmaf(hv, w.z, a2_);
            a3 = fmaf(hv, w.w, a3);
        }
        float4 o = make_float4(a0 * mk, a1 * mk, a2_ * mk, a3 * mk);
        *(float4*)&sX1[rl * XNP + d0] = o;
        *(float4*)(g_x1 + grow * DD + d0) = o;
    }
    __syncthreads();

    // Phase D: A[k] = b2a[k] + x1_row.W2aT[k];  Bneg[k] = -(xn_row.W2aT[k])
    {
        float x1r[DD], xnr[DD];
        const float4* x14 = (const float4*)&sX1[rl * XNP];
        const float4* xn4 = (const float4*)&sXn[rl * XNP];
        #pragma unroll
        for (int q = 0; q < 8; q++) {
            float4 v = x14[q];
            x1r[4*q+0] = v.x; x1r[4*q+1] = v.y; x1r[4*q+2] = v.z; x1r[4*q+3] = v.w;
            float4 u = xn4[q];
            xnr[4*q+0] = u.x; xnr[4*q+1] = u.y; xnr[4*q+2] = u.z; xnr[4*q+3] = u.w;
        }
        float* pA = g_A    + grow * KK;
        float* pB = g_Bneg + grow * KK;
        #pragma unroll
        for (int kk = 0; kk < 8; kk++) {
            const int k = p + 8 * kk;
            const float4* w4 = (const float4*)&sW2aT[k * WTP];
            float a = sb2a[k], b = 0.f;
            #pragma unroll
            for (int q = 0; q < 8; q++) {
                float4 v = w4[q];
                a = fmaf(x1r[4*q+0], v.x, a);  b = fmaf(xnr[4*q+0], v.x, b);
                a = fmaf(x1r[4*q+1], v.y, a);  b = fmaf(xnr[4*q+1], v.y, b);
                a = fmaf(x1r[4*q+2], v.z, a);  b = fmaf(xnr[4*q+2], v.z, b);
                a = fmaf(x1r[4*q+3], v.w, a);  b = fmaf(xnr[4*q+3], v.w, b);
            }
            pA[k] = a;
            pB[k] = -b;
        }
    }
}

// Kernel 2a: partial S matrix. Grid = SETS*16*2 = 1024 blocks x 128 threads.
// Block = (set, j-tile of 8, k-half of 32). Thread = row i. (unchanged)
__global__ __launch_bounds__(128) void k2a_smat()
{
    const int blk = blockIdx.x;
    const int s   = blk >> 5;
    const int jt  = (blk >> 1) & 15;
    const int kh  = blk & 1;
    const int j0  = jt * JT;
    const int tid = threadIdx.x;

    __shared__ __align__(16) float sBneg[JT * 32];
    __shared__ __align__(16) float sVh[32];
    __shared__ float sMk[JT];
    __shared__ float sc2;

    if (tid < 64) {
        const int m = tid >> 3, c4 = tid & 7;
        ((float4*)sBneg)[tid] =
            *(const float4*)(g_Bneg + ((size_t)s * NI + j0 + m) * KK + kh * 32 + c4 * 4);
    }
    if (tid >= 64 && tid < 96) sVh[tid - 64] = g_v2[kh * 32 + (tid - 64)];
    if (tid >= 96 && tid < 96 + JT) sMk[tid - 96] = g_mask[s * NI + j0 + (tid - 96)];
    if (tid == 127) sc2 = (kh == 0) ? g_c2 : 0.f;

    const bool iactive = (g_mask[s * NI + tid] != 0.f);

    unsigned long long a2[16];
    {
        const ulonglong2* pA =
            (const ulonglong2*)(g_A + ((size_t)s * NI + tid) * KK + kh * 32);
        #pragma unroll
        for (int t = 0; t < 8; t++) {
            ulonglong2 v = pA[t];
            a2[2*t] = v.x; a2[2*t+1] = v.y;
        }
    }
    __syncthreads();

    const unsigned long long C0_2 = pk2(0.7978845608028654f, 0.7978845608028654f);
    const unsigned long long C1_2 = pk2(0.044715f * 0.7978845608028654f,
                                        0.044715f * 0.7978845608028654f);
    const unsigned long long H_2  = pk2(0.5f, 0.5f);
    const float c2 = sc2;
    const ulonglong2* vp2 = (const ulonglong2*)sVh;

    float jsum = 0.f;
    #pragma unroll
    for (int m = 0; m < JT; m++) jsum += sMk[m];
    const bool act = iactive && (jsum != 0.f);

    unsigned long long acc2[JT];
    #pragma unroll
    for (int m = 0; m < JT; m++) acc2[m] = 0ull;

    if (act) {
        #pragma unroll
        for (int q = 0; q < 8; q++) {
            ulonglong2 vv = vp2[q];
            #pragma unroll
            for (int m = 0; m < JT; m++) {
                ulonglong2 bb = ((const ulonglong2*)(sBneg + m * 32))[q];
                acc2[m] = gelu2_dot(a2[2*q],   bb.x, vv.x, acc2[m], C0_2, C1_2, H_2);
                acc2[m] = gelu2_dot(a2[2*q+1], bb.y, vv.y, acc2[m], C0_2, C1_2, H_2);
            }
        }
    }
    float* pS = g_Sp + (((size_t)kh * SETS + s) * NI + j0) * NI + tid;
    #pragma unroll
    for (int m = 0; m < JT; m++) {
        float lo, hi;
        asm("mov.b64 {%0,%1}, %2;" : "=f"(lo), "=f"(hi) : "l"(acc2[m]));
        pS[m * NI] = act ? (lo + hi + c2) : 0.f;
    }
}

// Kernel 2b: aggregation. Grid = SETS*4 = 128 blocks x 128 threads. (unchanged)
__global__ __launch_bounds__(128) void k2b_agg(
    const float* __restrict__ x, const float* __restrict__ b3,
    float* __restrict__ out)
{
    const int s  = blockIdx.x >> 2;
    const int j0 = (blockIdx.x & 3) * 32;
    const int tid = threadIdx.x;

    __shared__ __align__(16) float sX1[NI * DD];
    __shared__ __align__(16) float sS[32 * NI];

    {
        const float4* pX1 = (const float4*)(g_x1 + (size_t)s * NI * DD);
        float4* sX14 = (float4*)sX1;
        for (int i = tid; i < NI * DD / 4; i += 128) sX14[i] = pX1[i];
        const float* p0 = g_Sp + ((size_t)s * NI + j0) * NI;
        const float* p1 = g_Sp + (((size_t)SETS + s) * NI + j0) * NI;
        for (int i = tid; i < 32 * NI; i += 128) sS[i] = p0[i] + p1[i];
    }
    __syncthreads();

    const int d  = tid & 31;
    const int jw = tid >> 5;
    float acc[8];
    #pragma unroll
    for (int m = 0; m < 8; m++) acc[m] = 0.f;

    #pragma unroll 4
    for (int i = 0; i < NI; i++) {
        const float xv = sX1[i * DD + d];
        #pragma unroll
        for (int m = 0; m < 8; m++)
            acc[m] = fmaf(sS[(jw * 8 + m) * NI + i], xv, acc[m]);
    }

    const float b3v = b3[0];
    #pragma unroll
    for (int m = 0; m < 8; m++) {
        const int jg = j0 + jw * 8 + m;
        const size_t oidx = ((size_t)s * NI + jg) * DD + d;
        out[oidx] = (acc[m] + b3v + x[oidx]) * g_mask[s * NI + jg];
    }
}

extern "C" void kernel_launch(void* const* d_in, const int* in_sizes, int n_in,
                              void* d_out, int out_size) {
    const float* x    = (const float*)d_in[0];
    const float* xsz  = (const float*)d_in[1];
    const float* W1a  = (const float*)d_in[2];
    const float* b1a  = (const float*)d_in[3];
    const float* W1b  = (const float*)d_in[4];
    const float* b1b  = (const float*)d_in[5];
    const float* W2a  = (const float*)d_in[6];
    const float* b2a  = (const float*)d_in[7];
    const float* W2b  = (const float*)d_in[8];
    const float* b2b  = (const float*)d_in[9];
    const float* w3   = (const float*)d_in[10];
    const float* b3   = (const float*)d_in[11];
    float* out = (float*)d_out;

    k0_stats<<<SETS, 128>>>(x, xsz, W2b, b2b, w3);
    k1_prep<<<SETS * 8, 128>>>(x, W1a, b1a, W1b, b1b, W2a, b2a);
    k2a_smat<<<SETS * 32, 128>>>();
    k2b_agg<<<SETS * 4, 128>>>(x, b3, out);
}